// round 7
// baseline (speedup 1.0000x reference)
#include <cuda_runtime.h>
#include <cstdint>

// Problem constants
#define B_ROWS   65536
#define K1       1024
#define K2       512
#define K3       768
#define NPAIRS   1152                  // (K1+K2+K3)/2
#define RANK     10
#define OUTDIM   512

// ---- kernel 1 (rank projection) ----
#define T1       192
#define GRID1    304                   // 2 CTAs/SM
#define NWARPS   (GRID1 * (T1 / 32))   // 1824
#define NGROUPS  (B_ROWS / 4)          // 16384 groups of 4 rows

#define FS_ELEMS (RANK * NPAIRS)       // 11520 float2
#define SMEM1    (FS_ELEMS * 8)        // 92160 B

// chunk counts (64-float chunks) per segment
#define NC1      (K1 / 64)             // 16
#define NC2      (K2 / 64)             // 8
#define NC3      (K3 / 64)             // 12

// ---- kernel 2 (out = y @ fout^T) ----
#define T2       256
#define RTILE    64
#define GRID2    (B_ROWS / RTILE)      // 1024

typedef unsigned long long u64;

// scratch for the intermediate y[B, RANK]
__device__ float y_buf[(size_t)B_ROWS * RANK];

// ---------- f32x2 packed helpers ----------
__device__ __forceinline__ u64 pk2(float lo, float hi) {
    u64 r; asm("mov.b64 %0, {%1, %2};" : "=l"(r) : "f"(lo), "f"(hi)); return r;
}
__device__ __forceinline__ void upk2(u64 v, float& lo, float& hi) {
    asm("mov.b64 {%0, %1}, %2;" : "=f"(lo), "=f"(hi) : "l"(v));
}
__device__ __forceinline__ u64 fma2(u64 a, u64 b, u64 c) {
    u64 d; asm("fma.rn.f32x2 %0, %1, %2, %3;" : "=l"(d) : "l"(a), "l"(b), "l"(c));
    return d;
}
__device__ __forceinline__ float hadd2(u64 v) {
    float lo, hi; upk2(v, lo, hi); return lo + hi;
}

// 4 row pointers into one x segment, pre-offset by lane kL
struct Quad { const ulonglong2 *p0, *p1, *p2, *p3; };

__device__ __forceinline__ Quad mkquad(const float* x, int row0, int K, int kL) {
    Quad q;
    q.p0 = reinterpret_cast<const ulonglong2*>(x + (size_t)(row0    ) * K) + kL;
    q.p1 = reinterpret_cast<const ulonglong2*>(x + (size_t)(row0 + 1) * K) + kL;
    q.p2 = reinterpret_cast<const ulonglong2*>(x + (size_t)(row0 + 2) * K) + kL;
    q.p3 = reinterpret_cast<const ulonglong2*>(x + (size_t)(row0 + 3) * K) + kL;
    return q;
}

// consume buf stage S against factor pointer FP (5 LDS.128 + 40 fma2)
#define CONSUME(S, FP) do {                                              \
    ulonglong2 v0 = buf[S][0], v1 = buf[S][1],                           \
               v2 = buf[S][2], v3 = buf[S][3];                           \
    const ulonglong2* _fp = (FP);                                        \
    _Pragma("unroll")                                                    \
    for (int j = 0; j < 5; j++) {                                        \
        ulonglong2 fv = _fp[j * (NPAIRS / 2)];                           \
        acc[0][j] = fma2(v0.x, fv.x, acc[0][j]);                         \
        acc[0][j] = fma2(v0.y, fv.y, acc[0][j]);                         \
        acc[1][j] = fma2(v1.x, fv.x, acc[1][j]);                         \
        acc[1][j] = fma2(v1.y, fv.y, acc[1][j]);                         \
        acc[2][j] = fma2(v2.x, fv.x, acc[2][j]);                         \
        acc[2][j] = fma2(v2.y, fv.y, acc[2][j]);                         \
        acc[3][j] = fma2(v3.x, fv.x, acc[3][j]);                         \
        acc[3][j] = fma2(v3.y, fv.y, acc[3][j]);                         \
    }                                                                    \
} while (0)

#define REFILL(S, Q, C) do {                                             \
    buf[S][0] = (Q).p0[(C) * 16];                                        \
    buf[S][1] = (Q).p1[(C) * 16];                                        \
    buf[S][2] = (Q).p2[(C) * 16];                                        \
    buf[S][3] = (Q).p3[(C) * 16];                                        \
} while (0)

// fold even/odd halves of acc into zt, zero acc
#define FOLD() do {                                                      \
    _Pragma("unroll") for (int i = 0; i < 4; i++)                        \
    _Pragma("unroll") for (int j = 0; j < 5; j++) {                      \
        zt[i][j] = hadd2(acc[i][j]); acc[i][j] = 0ull; }                 \
} while (0)

// butterfly-reduce zt over the 16-lane k-group
#define REDUCE() do {                                                    \
    _Pragma("unroll") for (int m = 8; m > 0; m >>= 1)                    \
    _Pragma("unroll") for (int i = 0; i < 4; i++)                        \
    _Pragma("unroll") for (int j = 0; j < 5; j++)                        \
        zt[i][j] += __shfl_xor_sync(0xffffffffu, zt[i][j], m);           \
} while (0)

extern "C" __global__ void __launch_bounds__(T1, 2)
arf_k1(const float* __restrict__ x1, const float* __restrict__ x2,
       const float* __restrict__ x3,
       const float* __restrict__ f1, const float* __restrict__ f2g,
       const float* __restrict__ f3)
{
    extern __shared__ float2 f_s[];    // [RANK][NPAIRS], k-pair packed

    const int tid = threadIdx.x;

    // factor repack: f_s[r*NPAIRS + kp] = (f_seg[2k][r], f_seg[2k+1][r])
    for (int idx = tid; idx < FS_ELEMS; idx += T1) {
        int r  = idx / NPAIRS;
        int kp = idx % NPAIRS;
        const float* f; int kloc;
        if (kp < K1 / 2)              { f = f1;  kloc = 2 * kp; }
        else if (kp < (K1 + K2) / 2)  { f = f2g; kloc = 2 * (kp - K1 / 2); }
        else                          { f = f3;  kloc = 2 * (kp - (K1 + K2) / 2); }
        f_s[idx] = make_float2(f[kloc * RANK + r], f[(kloc + 1) * RANK + r]);
    }
    __syncthreads();

    const ulonglong2* fsp = reinterpret_cast<const ulonglong2*>(f_s);

    const int lane = tid & 31;
    const int kL   = lane & 15;
    const int h    = lane >> 4;
    const int gw   = (blockIdx.x * T1 + tid) >> 5;

    // factor base offsets (ulonglong2 units) per segment for this lane
    const ulonglong2* FA = fsp + h * (5 * NPAIRS / 2) + kL;                  // seg1
    const ulonglong2* FB = FA + (K1 / 2) / 2;                                // seg2 (+256)
    const ulonglong2* FC = FA + ((K1 + K2) / 2) / 2;                         // seg3 (+384)

    u64 acc[4][5];
#pragma unroll
    for (int i = 0; i < 4; i++)
#pragma unroll
        for (int j = 0; j < 5; j++) acc[i][j] = 0ull;

    ulonglong2 buf[2][4];
    float p[4][5], zt[4][5];

    // prologue: preload first group's x1 chunks 0,1
    Quad qa = mkquad(x1, gw * 4, K1, kL);
    if (gw < NGROUPS) { REFILL(0, qa, 0); REFILL(1, qa, 1); }

    for (int g = gw; g < NGROUPS; g += NWARPS) {
        const int row0 = g * 4;
        const int gn   = (g + NWARPS < NGROUPS) ? g + NWARPS : g;

        Quad qb = mkquad(x2, row0,  K2, kL);
        Quad qc = mkquad(x3, row0,  K3, kL);
        Quad qn = mkquad(x1, gn * 4, K1, kL);

        // ---- segment 1 (x1, 16 chunks) ----
#pragma unroll 2
        for (int c = 0; c < NC1 - 2; c++) {
            CONSUME(c & 1, FA + c * 16);
            REFILL(c & 1, qa, c + 2);
        }
        CONSUME(0, FA + (NC1 - 2) * 16); REFILL(0, qb, 0);   // lead into x2
        CONSUME(1, FA + (NC1 - 1) * 16); REFILL(1, qb, 1);
        FOLD(); REDUCE();                                     // overlaps x2 flight
#pragma unroll
        for (int i = 0; i < 4; i++)
#pragma unroll
            for (int j = 0; j < 5; j++) p[i][j] = zt[i][j];

        // ---- segment 2 (x2, 8 chunks) ----
#pragma unroll 2
        for (int c = 0; c < NC2 - 2; c++) {
            CONSUME(c & 1, FB + c * 16);
            REFILL(c & 1, qb, c + 2);
        }
        CONSUME(0, FB + (NC2 - 2) * 16); REFILL(0, qc, 0);   // lead into x3
        CONSUME(1, FB + (NC2 - 1) * 16); REFILL(1, qc, 1);
        FOLD(); REDUCE();
#pragma unroll
        for (int i = 0; i < 4; i++)
#pragma unroll
            for (int j = 0; j < 5; j++) p[i][j] *= zt[i][j];

        // ---- segment 3 (x3, 12 chunks) ----
#pragma unroll 2
        for (int c = 0; c < NC3 - 2; c++) {
            CONSUME(c & 1, FC + c * 16);
            REFILL(c & 1, qc, c + 2);
        }
        CONSUME(0, FC + (NC3 - 2) * 16); REFILL(0, qn, 0);   // lead into next group
        CONSUME(1, FC + (NC3 - 1) * 16); REFILL(1, qn, 1);
        qa = qn;
        FOLD(); REDUCE();
#pragma unroll
        for (int i = 0; i < 4; i++)
#pragma unroll
            for (int j = 0; j < 5; j++) p[i][j] *= zt[i][j];

        // lane (h*16 + i) writes row row0+i, ranks h*5..h*5+4
#pragma unroll
        for (int i = 0; i < 4; i++) {
            if (kL == i) {
#pragma unroll
                for (int j = 0; j < 5; j++)
                    y_buf[(size_t)(row0 + i) * RANK + h * 5 + j] = p[i][j];
            }
        }
    }
}

// out[b, c] = sum_j y[b, j] * fout[c, j]
// 256 threads; thread t owns adjacent cols (2t, 2t+1) -> one STG.64 per row;
// 64-row tile; y transposed in smem so a row-pair is one LDS.64 broadcast;
// fout lives in registers (packed duplicate per column).
extern "C" __global__ void __launch_bounds__(T2)
arf_k2(const float* __restrict__ fout, float* __restrict__ out)
{
    __shared__ __align__(16) float yt[RANK][RTILE];   // transposed y tile

    const int t    = threadIdx.x;
    const int c0   = 2 * t;
    const int base = blockIdx.x * RTILE;

    u64 foA[RANK], foB[RANK];
#pragma unroll
    for (int j = 0; j < RANK; j++) {
        float a = fout[(size_t)c0 * RANK + j];
        float b = fout[(size_t)(c0 + 1) * RANK + j];
        foA[j] = pk2(a, a);
        foB[j] = pk2(b, b);
    }

    for (int idx = t; idx < RTILE * RANK; idx += T2) {
        int r = idx / RANK, j = idx % RANK;       // coalesced y_buf read
        yt[j][r] = y_buf[(size_t)base * RANK + idx];
    }
    __syncthreads();

#pragma unroll 4
    for (int rp = 0; rp < RTILE / 2; rp++) {
        u64 yv[RANK];
#pragma unroll
        for (int j = 0; j < RANK; j++)
            yv[j] = *reinterpret_cast<const u64*>(&yt[j][2 * rp]);  // broadcast

        u64 a = 0ull, b = 0ull;
#pragma unroll
        for (int j = 0; j < RANK; j++) {
            a = fma2(yv[j], foA[j], a);
            b = fma2(yv[j], foB[j], b);
        }
        float la, ha, lb, hb;
        upk2(a, la, ha);
        upk2(b, lb, hb);
        float2* o0 = reinterpret_cast<float2*>(out + (size_t)(base + 2 * rp) * OUTDIM);
        float2* o1 = reinterpret_cast<float2*>(out + (size_t)(base + 2 * rp + 1) * OUTDIM);
        o0[t] = make_float2(la, lb);   // STG.64, coalesced
        o1[t] = make_float2(ha, hb);
    }
}

extern "C" void kernel_launch(void* const* d_in, const int* in_sizes, int n_in,
                              void* d_out, int out_size)
{
    const float* x1   = (const float*)d_in[0];
    const float* x2   = (const float*)d_in[1];
    const float* x3   = (const float*)d_in[2];
    const float* f1   = (const float*)d_in[3];
    const float* f2   = (const float*)d_in[4];
    const float* f3   = (const float*)d_in[5];
    const float* fout = (const float*)d_in[6];
    float* out = (float*)d_out;

    cudaFuncSetAttribute(arf_k1,
                         cudaFuncAttributeMaxDynamicSharedMemorySize, SMEM1);

    arf_k1<<<GRID1, T1, SMEM1>>>(x1, x2, x3, f1, f2, f3);
    arf_k2<<<GRID2, T2>>>(fout, out);
}